// round 3
// baseline (speedup 1.0000x reference)
#include <cuda_runtime.h>

#define DIM 64
#define KC  512

// Loss accumulator scratch (no allocations allowed; zeroed by init kernel each launch).
__device__ double g_loss_sum;

__global__ void vq_init_kernel() {
    g_loss_sum = 0.0;
}

__global__ __launch_bounds__(512, 1)
void vq_main_kernel(const float* __restrict__ z,
                    const float* __restrict__ emb,
                    float* __restrict__ out,
                    int M,
                    long long q_off, long long i_off,
                    int has_q, int has_idx)
{
    extern __shared__ float sm[];          // [KC*DIM] codebook, then [KC] ||e||^2
    float* se = sm + KC * DIM;

    // Cooperative codebook load (128 KB) into smem.
    for (int i = threadIdx.x; i < KC * DIM / 4; i += blockDim.x)
        ((float4*)sm)[i] = ((const float4*)emb)[i];
    __syncthreads();

    // ||e_k||^2, sequential rn accumulation (match reference rounding style).
    if (threadIdx.x < KC) {
        const float* e = sm + threadIdx.x * DIM;
        float s = 0.0f;
        #pragma unroll
        for (int d = 0; d < DIM; d++)
            s = __fadd_rn(s, __fmul_rn(e[d], e[d]));
        se[threadIdx.x] = s;
    }
    __syncthreads();

    int row = blockIdx.x * blockDim.x + threadIdx.x;
    double lacc = 0.0;

    if (row < M) {
        // z-row in registers. z itself is 16B-aligned (row*DIM*4 is a multiple of 256B).
        float zr[DIM];
        const float4* zp = (const float4*)(z + (long long)row * DIM);
        #pragma unroll
        for (int i = 0; i < DIM / 4; i++) {
            float4 v = zp[i];
            zr[4*i+0] = v.x; zr[4*i+1] = v.y; zr[4*i+2] = v.z; zr[4*i+3] = v.w;
        }

        // ||z||^2 sequential rn.
        float sz = 0.0f;
        #pragma unroll
        for (int d = 0; d < DIM; d++)
            sz = __fadd_rn(sz, __fmul_rn(zr[d], zr[d]));

        float best = 3.402823466e38f;
        int   bi   = 0;

        // 4 codes in flight: 4 independent FMA chains (ILP covers FFMA lat=4).
        for (int k = 0; k < KC; k += 4) {
            const float* eb = sm + k * DIM;
            float a0 = 0.0f, a1 = 0.0f, a2 = 0.0f, a3 = 0.0f;
            #pragma unroll
            for (int d = 0; d < DIM; d += 4) {
                float4 e0 = *(const float4*)(eb + 0*DIM + d);
                float4 e1 = *(const float4*)(eb + 1*DIM + d);
                float4 e2 = *(const float4*)(eb + 2*DIM + d);
                float4 e3 = *(const float4*)(eb + 3*DIM + d);
                a0 = __fmaf_rn(zr[d+0], e0.x, a0);
                a0 = __fmaf_rn(zr[d+1], e0.y, a0);
                a0 = __fmaf_rn(zr[d+2], e0.z, a0);
                a0 = __fmaf_rn(zr[d+3], e0.w, a0);
                a1 = __fmaf_rn(zr[d+0], e1.x, a1);
                a1 = __fmaf_rn(zr[d+1], e1.y, a1);
                a1 = __fmaf_rn(zr[d+2], e1.z, a1);
                a1 = __fmaf_rn(zr[d+3], e1.w, a1);
                a2 = __fmaf_rn(zr[d+0], e2.x, a2);
                a2 = __fmaf_rn(zr[d+1], e2.y, a2);
                a2 = __fmaf_rn(zr[d+2], e2.z, a2);
                a2 = __fmaf_rn(zr[d+3], e2.w, a2);
                a3 = __fmaf_rn(zr[d+0], e3.x, a3);
                a3 = __fmaf_rn(zr[d+1], e3.y, a3);
                a3 = __fmaf_rn(zr[d+2], e3.z, a3);
                a3 = __fmaf_rn(zr[d+3], e3.w, a3);
            }
            // dist = fl(fl(sz + se_k) - 2*dot)  — exact reference expression order.
            float d0 = __fsub_rn(__fadd_rn(sz, se[k+0]), 2.0f * a0);
            float d1 = __fsub_rn(__fadd_rn(sz, se[k+1]), 2.0f * a1);
            float d2 = __fsub_rn(__fadd_rn(sz, se[k+2]), 2.0f * a2);
            float d3 = __fsub_rn(__fadd_rn(sz, se[k+3]), 2.0f * a3);
            // Strict < keeps FIRST minimal index (jnp.argmin semantics).
            if (d0 < best) { best = d0; bi = k + 0; }
            if (d1 < best) { best = d1; bi = k + 1; }
            if (d2 < best) { best = d2; bi = k + 2; }
            if (d3 < best) { best = d3; bi = k + 3; }
        }

        // Emit quantized_st = fl(z + fl(q - z)) and loss term fl(st - z)^2.
        // NOTE: out+q_off is only 4B-aligned (q_off=1) -> scalar STG.32 only.
        const float* e = sm + bi * DIM;
        float* qdst = out + q_off + (long long)row * DIM;
        float lsum = 0.0f;
        #pragma unroll
        for (int d = 0; d < DIM; d++) {
            float q  = e[d];
            float zd = zr[d];
            float r  = __fsub_rn(q, zd);
            float st = __fadd_rn(zd, r);
            float df = __fsub_rn(st, zd);
            lsum = __fmaf_rn(df, df, lsum);
            if (has_q) qdst[d] = st;
        }
        lacc = (double)lsum;
        if (has_idx) out[i_off + row] = (float)bi;
    }

    // Block-level loss reduction in double, one global atomic per block.
    __shared__ double red[512];
    red[threadIdx.x] = lacc;
    __syncthreads();
    for (int s = blockDim.x >> 1; s > 0; s >>= 1) {
        if (threadIdx.x < (unsigned)s) red[threadIdx.x] += red[threadIdx.x + s];
        __syncthreads();
    }
    if (threadIdx.x == 0) atomicAdd(&g_loss_sum, red[0]);
}

__global__ void vq_fin_kernel(float* out, long long n_elems) {
    // loss = recon + 0.25*recon = 1.25 * mean((st - z)^2)
    out[0] = (float)(1.25 * (g_loss_sum / (double)n_elems));
}

extern "C" void kernel_launch(void* const* d_in, const int* in_sizes, int n_in,
                              void* d_out, int out_size)
{
    const float* z   = (const float*)d_in[0];
    const float* emb = (const float*)d_in[1];
    long long zn = in_sizes[0];
    // Defensive input-order check: embeddings table is exactly KC*DIM elements.
    if (n_in >= 2 && in_sizes[0] == KC * DIM && in_sizes[1] != KC * DIM) {
        z = (const float*)d_in[1];
        emb = (const float*)d_in[0];
        zn = in_sizes[1];
    }
    int M = (int)(zn / DIM);
    float* out = (float*)d_out;

    // Output layout detection: [loss][quantized_st][indices-as-float] expected.
    long long q_off = 1, i_off = 1 + zn;
    int has_loss = 1, has_q = 1, has_idx = 1;
    long long osz = (long long)out_size;
    if (osz == 1 + zn + (long long)M)      { has_loss = 1; has_q = 1; has_idx = 1; q_off = 1; i_off = 1 + zn; }
    else if (osz == zn + (long long)M)     { has_loss = 0; has_q = 1; has_idx = 1; q_off = 0; i_off = zn; }
    else if (osz == zn)                    { has_loss = 0; has_q = 1; has_idx = 0; q_off = 0; }
    else if (osz == 1)                     { has_loss = 1; has_q = 0; has_idx = 0; }
    /* else: default full layout above */

    size_t smem_bytes = (size_t)(KC * DIM + KC) * sizeof(float);
    cudaFuncSetAttribute(vq_main_kernel,
                         cudaFuncAttributeMaxDynamicSharedMemorySize,
                         (int)smem_bytes);

    if (has_loss) vq_init_kernel<<<1, 1>>>();
    int blocks = (M + 511) / 512;
    vq_main_kernel<<<blocks, 512, smem_bytes>>>(z, emb, out, M,
                                                q_off, i_off, has_q, has_idx);
    if (has_loss) vq_fin_kernel<<<1, 1>>>(out, zn);
}